// round 1
// baseline (speedup 1.0000x reference)
#include <cuda_runtime.h>
#include <cuda_bf16.h>

// Swin window attention, fp32 baseline.
// B=64, H=W=56, C=128, heads=4, hd=32, ws=7, L=49, 64 windows/img.
// Pipeline: qkv_gemm (scatter to window layout) -> attn (per window-head) -> proj_gemm.

#define TOKENS   200704        // 64*56*56
#define WH_TOTAL 16384         // 64 imgs * 64 windows * 4 heads
#define QKV_ELEMS (3ull * 16384ull * 49ull * 32ull)   // 77,070,336
#define ATT_ELEMS ((size_t)TOKENS * 128)              // 25,690,112

__device__ float g_qkv[QKV_ELEMS];   // [(s*16384 + wh)*49 + l]*32 + d
__device__ float g_att[ATT_ELEMS];   // [b,h,w,c] pre-projection

// ---------------------------------------------------------------------------
// Kernel 1: QKV GEMM.  A = x [200704, 128], W = qkv_w [128, 384].
// Tile 128x128x8, 256 threads, 8x8 per thread. Epilogue scatters into window
// layout: col = s*128 + head*32 + d ; row token -> (wh, l).
// ---------------------------------------------------------------------------
__global__ __launch_bounds__(256) void qkv_gemm(
    const float* __restrict__ A, const float* __restrict__ W,
    const float* __restrict__ bias)
{
    __shared__ float As[8][128];
    __shared__ float Bs[8][128];
    const int N = 384;
    int tid = threadIdx.x;
    int bm  = blockIdx.x;          // 1568 row tiles
    int s   = blockIdx.y;          // 0=q,1=k,2=v (128-col tiles)
    int ty = tid >> 4, tx = tid & 15;
    int arow = tid >> 1, aseg = (tid & 1) * 4;
    int brow = tid >> 5, bcol = (tid & 31) * 4;
    const float* Ap = A + ((size_t)(bm * 128 + arow)) * 128 + aseg;
    const float* Wp = W + (size_t)brow * N + s * 128 + bcol;

    float acc[8][8] = {};
    for (int k0 = 0; k0 < 128; k0 += 8) {
        float4 av = *(const float4*)(Ap + k0);
        As[aseg + 0][arow] = av.x; As[aseg + 1][arow] = av.y;
        As[aseg + 2][arow] = av.z; As[aseg + 3][arow] = av.w;
        *(float4*)&Bs[brow][bcol] = *(const float4*)(Wp + (size_t)k0 * N);
        __syncthreads();
#pragma unroll
        for (int k = 0; k < 8; k++) {
            float a[8], b[8];
#pragma unroll
            for (int i = 0; i < 8; i++) a[i] = As[k][ty * 8 + i];
#pragma unroll
            for (int j = 0; j < 8; j++) b[j] = Bs[k][tx * 8 + j];
#pragma unroll
            for (int i = 0; i < 8; i++)
#pragma unroll
                for (int j = 0; j < 8; j++)
                    acc[i][j] += a[i] * b[j];
        }
        __syncthreads();
    }

    // Epilogue: scatter. Within this block, s = blockIdx.y, head = tx/4,
    // d0 = (tx%4)*8 (8 consecutive d's per thread -> 2 float4 stores).
    int head = tx >> 2;
    int d0   = (tx & 3) * 8;
    int colb = s * 128 + tx * 8;
    float bb[8];
#pragma unroll
    for (int j = 0; j < 8; j++) bb[j] = bias[colb + j];

#pragma unroll
    for (int i = 0; i < 8; i++) {
        int m    = bm * 128 + ty * 8 + i;          // token id
        int bimg = m / 3136;
        int rem  = m - bimg * 3136;
        int y    = rem / 56,  xx = rem - y * 56;
        int nhi  = y / 7,     wy = y - nhi * 7;
        int nwi  = xx / 7,    wx = xx - nwi * 7;
        int wh   = ((bimg * 64 + nhi * 8 + nwi) << 2) + head;
        int l    = wy * 7 + wx;
        size_t dst = ((size_t)(s * 16384 + wh) * 49 + l) * 32 + d0;
        float4 v0 = make_float4(acc[i][0] + bb[0], acc[i][1] + bb[1],
                                acc[i][2] + bb[2], acc[i][3] + bb[3]);
        float4 v1 = make_float4(acc[i][4] + bb[4], acc[i][5] + bb[5],
                                acc[i][6] + bb[6], acc[i][7] + bb[7]);
        *(float4*)&g_qkv[dst]     = v0;
        *(float4*)&g_qkv[dst + 4] = v1;
    }
}

// ---------------------------------------------------------------------------
// Kernel 2: attention, one block per (window, head). 256 threads.
// S = scale*Q@K^T + bias + mask ; softmax rows ; O = P@V -> g_att [b,h,w,c].
// L=49 padded to 64 for regular 4x4 register tiling.
// ---------------------------------------------------------------------------
__global__ __launch_bounds__(256) void attn_kernel(
    const int* __restrict__ relidx, const float* __restrict__ mask,
    const float* __restrict__ relt)
{
    __shared__ float sq [64][33];
    __shared__ float skT[32][65];   // k transposed: [d][l]
    __shared__ float sv [64][33];
    __shared__ float S  [64][65];

    int tid  = threadIdx.x;
    int wh   = blockIdx.x;
    int head = wh & 3;
    int widx = wh >> 2;
    int bimg = widx >> 6;
    int win  = widx & 63;
    const float* qp = g_qkv + (size_t)wh * 1568;
    const float* kp = g_qkv + (size_t)(16384 + wh) * 1568;
    const float* vp = g_qkv + (size_t)(2 * 16384 + wh) * 1568;
    const float* maskp = mask + (size_t)win * 2401;

    // Load q/k/v (rows >= 49 zero-padded)
    for (int idx = tid; idx < 512; idx += 256) {
        int l = idx >> 3, c4 = (idx & 7) << 2;
        float4 q4 = make_float4(0.f, 0.f, 0.f, 0.f), k4 = q4, v4 = q4;
        if (l < 49) {
            q4 = *(const float4*)(qp + l * 32 + c4);
            k4 = *(const float4*)(kp + l * 32 + c4);
            v4 = *(const float4*)(vp + l * 32 + c4);
        }
        sq[l][c4] = q4.x; sq[l][c4 + 1] = q4.y; sq[l][c4 + 2] = q4.z; sq[l][c4 + 3] = q4.w;
        skT[c4][l] = k4.x; skT[c4 + 1][l] = k4.y; skT[c4 + 2][l] = k4.z; skT[c4 + 3][l] = k4.w;
        sv[l][c4] = v4.x; sv[l][c4 + 1] = v4.y; sv[l][c4 + 2] = v4.z; sv[l][c4 + 3] = v4.w;
    }
    __syncthreads();

    // ---- S = scale * Q @ K^T + bias + mask  (4x4 tiles on 64x64) ----
    {
        int ti = (tid >> 4) << 2;
        int tj = (tid & 15) << 2;
        float acc[4][4] = {};
#pragma unroll
        for (int d = 0; d < 32; ++d) {
            float a0 = sq[ti][d], a1 = sq[ti + 1][d], a2 = sq[ti + 2][d], a3 = sq[ti + 3][d];
            float b0 = skT[d][tj], b1 = skT[d][tj + 1], b2 = skT[d][tj + 2], b3 = skT[d][tj + 3];
            acc[0][0] += a0 * b0; acc[0][1] += a0 * b1; acc[0][2] += a0 * b2; acc[0][3] += a0 * b3;
            acc[1][0] += a1 * b0; acc[1][1] += a1 * b1; acc[1][2] += a1 * b2; acc[1][3] += a1 * b3;
            acc[2][0] += a2 * b0; acc[2][1] += a2 * b1; acc[2][2] += a2 * b2; acc[2][3] += a2 * b3;
            acc[3][0] += a3 * b0; acc[3][1] += a3 * b1; acc[3][2] += a3 * b2; acc[3][3] += a3 * b3;
        }
        const float scale = 0.17677669529663687f;  // 32^-0.5
#pragma unroll
        for (int r = 0; r < 4; r++) {
            int i = ti + r;
            if (i < 49) {
#pragma unroll
                for (int c = 0; c < 4; c++) {
                    int j = tj + c;
                    if (j < 49) {
                        int ij = i * 49 + j;
                        S[i][j] = acc[r][c] * scale
                                + relt[(relidx[ij] << 2) + head] + maskp[ij];
                    }
                }
            }
        }
    }
    __syncthreads();

    // ---- softmax over j (rows < 49), zero pad cols ----
    if (tid < 49) {
        float mx = -1e30f;
        for (int j = 0; j < 49; j++) mx = fmaxf(mx, S[tid][j]);
        float sum = 0.f;
        for (int j = 0; j < 49; j++) { float e = __expf(S[tid][j] - mx); S[tid][j] = e; sum += e; }
        float inv = 1.f / sum;
        for (int j = 0; j < 49; j++) S[tid][j] *= inv;
        for (int j = 49; j < 64; j++) S[tid][j] = 0.f;
    }
    __syncthreads();

    // ---- O = P @ V  (4 rows x 2 d per thread) ----
    {
        int pi = (tid >> 4) << 2;
        int pd = (tid & 15) << 1;
        float o[4][2] = {};
        for (int j = 0; j < 49; ++j) {
            float v0 = sv[j][pd], v1 = sv[j][pd + 1];
            float p0 = S[pi][j], p1 = S[pi + 1][j], p2 = S[pi + 2][j], p3 = S[pi + 3][j];
            o[0][0] += p0 * v0; o[0][1] += p0 * v1;
            o[1][0] += p1 * v0; o[1][1] += p1 * v1;
            o[2][0] += p2 * v0; o[2][1] += p2 * v1;
            o[3][0] += p3 * v0; o[3][1] += p3 * v1;
        }
        int ybase = (win >> 3) * 7;
        int xbase = (win & 7) * 7;
#pragma unroll
        for (int r = 0; r < 4; r++) {
            int i = pi + r;
            if (i < 49) {
                int wy = i / 7, wx = i - wy * 7;
                size_t off = (((size_t)(bimg * 56 + ybase + wy)) * 56 + (xbase + wx)) * 128
                           + head * 32 + pd;
                *(float2*)&g_att[off] = make_float2(o[r][0], o[r][1]);
            }
        }
    }
}

// ---------------------------------------------------------------------------
// Kernel 3: projection GEMM. A = g_att [200704,128], W = proj_w [128,128].
// ---------------------------------------------------------------------------
__global__ __launch_bounds__(256) void proj_gemm(
    const float* __restrict__ W, const float* __restrict__ bias,
    float* __restrict__ out)
{
    __shared__ float As[8][128];
    __shared__ float Bs[8][128];
    const int N = 128;
    int tid = threadIdx.x;
    int bm  = blockIdx.x;
    int ty = tid >> 4, tx = tid & 15;
    int arow = tid >> 1, aseg = (tid & 1) * 4;
    int brow = tid >> 5, bcol = (tid & 31) * 4;
    const float* Ap = g_att + ((size_t)(bm * 128 + arow)) * 128 + aseg;
    const float* Wp = W + (size_t)brow * N + bcol;

    float acc[8][8] = {};
    for (int k0 = 0; k0 < 128; k0 += 8) {
        float4 av = *(const float4*)(Ap + k0);
        As[aseg + 0][arow] = av.x; As[aseg + 1][arow] = av.y;
        As[aseg + 2][arow] = av.z; As[aseg + 3][arow] = av.w;
        *(float4*)&Bs[brow][bcol] = *(const float4*)(Wp + (size_t)k0 * N);
        __syncthreads();
#pragma unroll
        for (int k = 0; k < 8; k++) {
            float a[8], b[8];
#pragma unroll
            for (int i = 0; i < 8; i++) a[i] = As[k][ty * 8 + i];
#pragma unroll
            for (int j = 0; j < 8; j++) b[j] = Bs[k][tx * 8 + j];
#pragma unroll
            for (int i = 0; i < 8; i++)
#pragma unroll
                for (int j = 0; j < 8; j++)
                    acc[i][j] += a[i] * b[j];
        }
        __syncthreads();
    }

    float bb[8];
#pragma unroll
    for (int j = 0; j < 8; j++) bb[j] = bias[tx * 8 + j];
#pragma unroll
    for (int i = 0; i < 8; i++) {
        int m = bm * 128 + ty * 8 + i;
        size_t dst = (size_t)m * 128 + tx * 8;
        float4 v0 = make_float4(acc[i][0] + bb[0], acc[i][1] + bb[1],
                                acc[i][2] + bb[2], acc[i][3] + bb[3]);
        float4 v1 = make_float4(acc[i][4] + bb[4], acc[i][5] + bb[5],
                                acc[i][6] + bb[6], acc[i][7] + bb[7]);
        *(float4*)&out[dst]     = v0;
        *(float4*)&out[dst + 4] = v1;
    }
}

// ---------------------------------------------------------------------------
extern "C" void kernel_launch(void* const* d_in, const int* in_sizes, int n_in,
                              void* d_out, int out_size)
{
    const float* x      = nullptr;
    const int*   relidx = nullptr;
    const float* mask   = nullptr;
    const float* qkv_w  = nullptr;
    const float* qkv_b  = nullptr;
    const float* relt   = nullptr;
    const float* proj_w = nullptr;
    const float* proj_b = nullptr;

    // All input sizes are distinct -> identify by element count (robust to
    // whether the scalar window_size appears as an input).
    for (int i = 0; i < n_in; i++) {
        switch (in_sizes[i]) {
            case 25690112: x      = (const float*)d_in[i]; break;  // [64,56,56,128]
            case 2401:     relidx = (const int*)  d_in[i]; break;  // [49*49]
            case 153664:   mask   = (const float*)d_in[i]; break;  // [1,64,1,49,49]
            case 49152:    qkv_w  = (const float*)d_in[i]; break;  // [128,384]
            case 384:      qkv_b  = (const float*)d_in[i]; break;
            case 676:      relt   = (const float*)d_in[i]; break;  // [169,4]
            case 16384:    proj_w = (const float*)d_in[i]; break;  // [128,128]
            case 128:      proj_b = (const float*)d_in[i]; break;
            default: break;  // window_size scalar
        }
    }

    dim3 g1(TOKENS / 128, 3);
    qkv_gemm<<<g1, 256>>>(x, qkv_w, qkv_b);

    attn_kernel<<<WH_TOTAL, 256>>>(relidx, mask, relt);

    dim3 g3(TOKENS / 128, 1);
    proj_gemm<<<g3, 256>>>(proj_w, proj_b, (float*)d_out);
}

// round 3
// speedup vs baseline: 1.2313x; 1.2313x over previous
#include <cuda_runtime.h>
#include <cuda_bf16.h>
#include <cstdint>

// Swin window attention. R3: qkv/proj GEMMs via mma.sync tf32 (sm_100 non-'a'
// toolchain => no tcgen05; fallback HMMA tensor path). Attention fp32.
// B=64, H=W=56, C=128, heads=4, hd=32, ws=7, L=49.

#define TOKENS   200704
#define WH_TOTAL 16384
#define QKV_ELEMS (3ull * 16384ull * 49ull * 32ull)
#define ATT_ELEMS ((size_t)TOKENS * 128)

__device__ float g_qkv[QKV_ELEMS];   // [(s*16384 + wh)*49 + l]*32 + d
__device__ float g_att[ATT_ELEMS];   // [b,h,w,c] pre-projection

// ---------------------------------------------------------------------------
__device__ __forceinline__ uint32_t f2tf32(float x) {
    uint32_t r;
    asm("cvt.rna.tf32.f32 %0, %1;" : "=r"(r) : "f"(x));
    return r;
}
__device__ __forceinline__ void mma_tf32(float (&d)[4], const uint32_t* a, const uint32_t* b) {
    asm volatile("mma.sync.aligned.m16n8k8.row.col.f32.tf32.tf32.f32 "
                 "{%0,%1,%2,%3}, {%4,%5,%6,%7}, {%8,%9}, {%0,%1,%2,%3};"
                 : "+f"(d[0]), "+f"(d[1]), "+f"(d[2]), "+f"(d[3])
                 : "r"(a[0]), "r"(a[1]), "r"(a[2]), "r"(a[3]), "r"(b[0]), "r"(b[1]));
}

// Smem geometry: A[128][132] (stride 132 -> lane bank 4g+t conflict-free),
// B[128][136] (stride 8t+g conflict-free).
#define A_STR 132
#define B_STR 136
#define SM_A_BYTES (128 * A_STR * 4)          // 67584
#define SM_B_OFF   SM_A_BYTES
#define SM_TOTAL   (SM_A_BYTES + 128 * B_STR * 4)  // 137216

// ---------------------------------------------------------------------------
// QKV GEMM: grid=1568, 256 threads (8 warps: 2m x 4n). A tile resident,
// loop s=0..2 over the three 128-col output groups. Scatter into g_qkv.
// ---------------------------------------------------------------------------
__global__ __launch_bounds__(256) void qkv_gemm_mma(
    const float* __restrict__ A, const float* __restrict__ W,
    const float* __restrict__ bias)
{
    extern __shared__ uint32_t sm[];
    uint32_t* As = sm;
    uint32_t* Bs = sm + 128 * A_STR;

    int tid = threadIdx.x, bm = blockIdx.x;
    int lane = tid & 31, warp = tid >> 5;
    int g = lane >> 2, t = lane & 3;
    int m0 = (warp >> 2) * 64, n0 = (warp & 3) * 32;
    int head = warp & 3;

    // Load A tile (converted to tf32 bits)
    {
        const float4* Ap = (const float4*)(A + (size_t)bm * 128 * 128);
        for (int i = tid; i < 4096; i += 256) {
            int r = i >> 5, c = (i & 31) << 2;
            float4 v = Ap[i];
            uint32_t* d = &As[r * A_STR + c];
            d[0] = f2tf32(v.x); d[1] = f2tf32(v.y); d[2] = f2tf32(v.z); d[3] = f2tf32(v.w);
        }
    }

    // Precompute token mapping for this thread's 8 output rows
    int rows[8];
    int whbase[8], lwin8[8];
#pragma unroll
    for (int mt = 0; mt < 4; mt++)
#pragma unroll
        for (int h = 0; h < 2; h++) {
            int r = m0 + mt * 16 + g + h * 8;
            int m = bm * 128 + r;
            int bimg = m / 3136;
            int rem  = m - bimg * 3136;
            int y = rem / 56, xx = rem - y * 56;
            int nhi = y / 7,  wy = y - nhi * 7;
            int nwi = xx / 7, wx = xx - nwi * 7;
            rows[mt * 2 + h]   = r;
            whbase[mt * 2 + h] = (bimg * 64 + nhi * 8 + nwi) * 4 + head;
            lwin8[mt * 2 + h]  = wy * 7 + wx;
        }

    for (int s = 0; s < 3; s++) {
        __syncthreads();
        // Load B tile: Bs[k][n] = W[k][s*128+n]
        {
            const float* Wp = W + s * 128;
            for (int i = tid; i < 4096; i += 256) {
                int k = i >> 5, n = (i & 31) << 2;
                float4 v = *(const float4*)(Wp + (size_t)k * 384 + n);
                uint32_t* d = &Bs[k * B_STR + n];
                d[0] = f2tf32(v.x); d[1] = f2tf32(v.y); d[2] = f2tf32(v.z); d[3] = f2tf32(v.w);
            }
        }
        __syncthreads();

        float acc[4][4][4] = {};
#pragma unroll
        for (int k0 = 0; k0 < 128; k0 += 8) {
            uint32_t a[4][4], b[4][2];
#pragma unroll
            for (int mt = 0; mt < 4; mt++) {
                int base = (m0 + mt * 16 + g) * A_STR + k0 + t;
                a[mt][0] = As[base];
                a[mt][1] = As[base + 8 * A_STR];
                a[mt][2] = As[base + 4];
                a[mt][3] = As[base + 8 * A_STR + 4];
            }
#pragma unroll
            for (int nt = 0; nt < 4; nt++) {
                int base = (k0 + t) * B_STR + n0 + nt * 8 + g;
                b[nt][0] = Bs[base];
                b[nt][1] = Bs[base + 4 * B_STR];
            }
#pragma unroll
            for (int mt = 0; mt < 4; mt++)
#pragma unroll
                for (int nt = 0; nt < 4; nt++)
                    mma_tf32(acc[mt][nt], a[mt], b[nt]);
        }

        // Epilogue: scatter into g_qkv window layout
        float bb[4][2];
#pragma unroll
        for (int nt = 0; nt < 4; nt++) {
            int d = nt * 8 + 2 * t;
            bb[nt][0] = bias[s * 128 + head * 32 + d];
            bb[nt][1] = bias[s * 128 + head * 32 + d + 1];
        }
#pragma unroll
        for (int mt = 0; mt < 4; mt++)
#pragma unroll
            for (int h = 0; h < 2; h++) {
                int idx = mt * 2 + h;
                size_t dst0 = ((size_t)(s * 16384 + whbase[idx]) * 49 + lwin8[idx]) * 32;
#pragma unroll
                for (int nt = 0; nt < 4; nt++) {
                    int d = nt * 8 + 2 * t;
                    float2 v = make_float2(acc[mt][nt][2 * h]     + bb[nt][0],
                                           acc[mt][nt][2 * h + 1] + bb[nt][1]);
                    *(float2*)&g_qkv[dst0 + d] = v;
                }
            }
    }
}

// ---------------------------------------------------------------------------
// Projection GEMM: grid=1568, same core, N=128, linear output.
// ---------------------------------------------------------------------------
__global__ __launch_bounds__(256) void proj_gemm_mma(
    const float* __restrict__ W, const float* __restrict__ bias,
    float* __restrict__ out)
{
    extern __shared__ uint32_t sm[];
    uint32_t* As = sm;
    uint32_t* Bs = sm + 128 * A_STR;

    int tid = threadIdx.x, bm = blockIdx.x;
    int lane = tid & 31, warp = tid >> 5;
    int g = lane >> 2, t = lane & 3;
    int m0 = (warp >> 2) * 64, n0 = (warp & 3) * 32;

    {
        const float4* Ap = (const float4*)(g_att + (size_t)bm * 128 * 128);
        for (int i = tid; i < 4096; i += 256) {
            int r = i >> 5, c = (i & 31) << 2;
            float4 v = Ap[i];
            uint32_t* d = &As[r * A_STR + c];
            d[0] = f2tf32(v.x); d[1] = f2tf32(v.y); d[2] = f2tf32(v.z); d[3] = f2tf32(v.w);
        }
        for (int i = tid; i < 4096; i += 256) {
            int k = i >> 5, n = (i & 31) << 2;
            float4 v = *(const float4*)(W + (size_t)k * 128 + n);
            uint32_t* d = &Bs[k * B_STR + n];
            d[0] = f2tf32(v.x); d[1] = f2tf32(v.y); d[2] = f2tf32(v.z); d[3] = f2tf32(v.w);
        }
    }
    __syncthreads();

    float acc[4][4][4] = {};
#pragma unroll
    for (int k0 = 0; k0 < 128; k0 += 8) {
        uint32_t a[4][4], b[4][2];
#pragma unroll
        for (int mt = 0; mt < 4; mt++) {
            int base = (m0 + mt * 16 + g) * A_STR + k0 + t;
            a[mt][0] = As[base];
            a[mt][1] = As[base + 8 * A_STR];
            a[mt][2] = As[base + 4];
            a[mt][3] = As[base + 8 * A_STR + 4];
        }
#pragma unroll
        for (int nt = 0; nt < 4; nt++) {
            int base = (k0 + t) * B_STR + n0 + nt * 8 + g;
            b[nt][0] = Bs[base];
            b[nt][1] = Bs[base + 4 * B_STR];
        }
#pragma unroll
        for (int mt = 0; mt < 4; mt++)
#pragma unroll
            for (int nt = 0; nt < 4; nt++)
                mma_tf32(acc[mt][nt], a[mt], b[nt]);
    }

    float bb[4][2];
#pragma unroll
    for (int nt = 0; nt < 4; nt++) {
        int d = n0 + nt * 8 + 2 * t;
        bb[nt][0] = bias[d];
        bb[nt][1] = bias[d + 1];
    }
#pragma unroll
    for (int mt = 0; mt < 4; mt++)
#pragma unroll
        for (int h = 0; h < 2; h++) {
            int r = m0 + mt * 16 + g + h * 8;
            float* op = out + ((size_t)bm * 128 + r) * 128;
#pragma unroll
            for (int nt = 0; nt < 4; nt++) {
                int d = n0 + nt * 8 + 2 * t;
                float2 v = make_float2(acc[mt][nt][2 * h]     + bb[nt][0],
                                       acc[mt][nt][2 * h + 1] + bb[nt][1]);
                *(float2*)&op[d] = v;
            }
        }
}

// ---------------------------------------------------------------------------
// Attention (fp32), one block per (window, head). 256 threads.
// ---------------------------------------------------------------------------
__global__ __launch_bounds__(256) void attn_kernel(
    const int* __restrict__ relidx, const float* __restrict__ mask,
    const float* __restrict__ relt)
{
    __shared__ float sq [64][33];
    __shared__ float skT[32][65];
    __shared__ float sv [64][33];
    __shared__ float S  [64][65];

    int tid  = threadIdx.x;
    int wh   = blockIdx.x;
    int head = wh & 3;
    int widx = wh >> 2;
    int bimg = widx >> 6;
    int win  = widx & 63;
    const float* qp = g_qkv + (size_t)wh * 1568;
    const float* kp = g_qkv + (size_t)(16384 + wh) * 1568;
    const float* vp = g_qkv + (size_t)(2 * 16384 + wh) * 1568;
    const float* maskp = mask + (size_t)win * 2401;

    for (int idx = tid; idx < 512; idx += 256) {
        int l = idx >> 3, c4 = (idx & 7) << 2;
        float4 q4 = make_float4(0.f, 0.f, 0.f, 0.f), k4 = q4, v4 = q4;
        if (l < 49) {
            q4 = *(const float4*)(qp + l * 32 + c4);
            k4 = *(const float4*)(kp + l * 32 + c4);
            v4 = *(const float4*)(vp + l * 32 + c4);
        }
        sq[l][c4] = q4.x; sq[l][c4 + 1] = q4.y; sq[l][c4 + 2] = q4.z; sq[l][c4 + 3] = q4.w;
        skT[c4][l] = k4.x; skT[c4 + 1][l] = k4.y; skT[c4 + 2][l] = k4.z; skT[c4 + 3][l] = k4.w;
        sv[l][c4] = v4.x; sv[l][c4 + 1] = v4.y; sv[l][c4 + 2] = v4.z; sv[l][c4 + 3] = v4.w;
    }
    __syncthreads();

    // S = scale * Q @ K^T + bias + mask
    {
        int ti = (tid >> 4) << 2;
        int tj = (tid & 15) << 2;
        float acc[4][4] = {};
#pragma unroll
        for (int d = 0; d < 32; ++d) {
            float a0 = sq[ti][d], a1 = sq[ti + 1][d], a2 = sq[ti + 2][d], a3 = sq[ti + 3][d];
            float b0 = skT[d][tj], b1 = skT[d][tj + 1], b2 = skT[d][tj + 2], b3 = skT[d][tj + 3];
            acc[0][0] += a0 * b0; acc[0][1] += a0 * b1; acc[0][2] += a0 * b2; acc[0][3] += a0 * b3;
            acc[1][0] += a1 * b0; acc[1][1] += a1 * b1; acc[1][2] += a1 * b2; acc[1][3] += a1 * b3;
            acc[2][0] += a2 * b0; acc[2][1] += a2 * b1; acc[2][2] += a2 * b2; acc[2][3] += a2 * b3;
            acc[3][0] += a3 * b0; acc[3][1] += a3 * b1; acc[3][2] += a3 * b2; acc[3][3] += a3 * b3;
        }
        const float scale = 0.17677669529663687f;
#pragma unroll
        for (int r = 0; r < 4; r++) {
            int i = ti + r;
            if (i < 49) {
#pragma unroll
                for (int c = 0; c < 4; c++) {
                    int j = tj + c;
                    if (j < 49) {
                        int ij = i * 49 + j;
                        S[i][j] = acc[r][c] * scale
                                + relt[(relidx[ij] << 2) + head] + maskp[ij];
                    }
                }
            }
        }
    }
    __syncthreads();

    // softmax: 4 threads per row + quad shfl reduce
    {
        int row = tid >> 2, q = tid & 3;
        float mx = -1e30f, sum = 0.f;
        if (row < 49)
            for (int j = q; j < 49; j += 4) mx = fmaxf(mx, S[row][j]);
        mx = fmaxf(mx, __shfl_xor_sync(0xffffffffu, mx, 1));
        mx = fmaxf(mx, __shfl_xor_sync(0xffffffffu, mx, 2));
        if (row < 49)
            for (int j = q; j < 49; j += 4) { float e = __expf(S[row][j] - mx); S[row][j] = e; sum += e; }
        sum += __shfl_xor_sync(0xffffffffu, sum, 1);
        sum += __shfl_xor_sync(0xffffffffu, sum, 2);
        if (row < 49) {
            float inv = 1.f / sum;
            for (int j = q; j < 49; j += 4) S[row][j] *= inv;
        }
        if (tid < 64)
            for (int j = 49; j < 64; j++) S[tid][j] = 0.f;
    }
    __syncthreads();

    // O = P @ V
    {
        int pi = (tid >> 4) << 2;
        int pd = (tid & 15) << 1;
        float o[4][2] = {};
        for (int j = 0; j < 49; ++j) {
            float v0 = sv[j][pd], v1 = sv[j][pd + 1];
            float p0 = S[pi][j], p1 = S[pi + 1][j], p2 = S[pi + 2][j], p3 = S[pi + 3][j];
            o[0][0] += p0 * v0; o[0][1] += p0 * v1;
            o[1][0] += p1 * v0; o[1][1] += p1 * v1;
            o[2][0] += p2 * v0; o[2][1] += p2 * v1;
            o[3][0] += p3 * v0; o[3][1] += p3 * v1;
        }
        int ybase = (win >> 3) * 7;
        int xbase = (win & 7) * 7;
#pragma unroll
        for (int r = 0; r < 4; r++) {
            int i = pi + r;
            if (i < 49) {
                int wy = i / 7, wx = i - wy * 7;
                size_t off = (((size_t)(bimg * 56 + ybase + wy)) * 56 + (xbase + wx)) * 128
                           + head * 32 + pd;
                *(float2*)&g_att[off] = make_float2(o[r][0], o[r][1]);
            }
        }
    }
}

// ---------------------------------------------------------------------------
extern "C" void kernel_launch(void* const* d_in, const int* in_sizes, int n_in,
                              void* d_out, int out_size)
{
    const float* x      = nullptr;
    const int*   relidx = nullptr;
    const float* mask   = nullptr;
    const float* qkv_w  = nullptr;
    const float* qkv_b  = nullptr;
    const float* relt   = nullptr;
    const float* proj_w = nullptr;
    const float* proj_b = nullptr;

    for (int i = 0; i < n_in; i++) {
        switch (in_sizes[i]) {
            case 25690112: x      = (const float*)d_in[i]; break;
            case 2401:     relidx = (const int*)  d_in[i]; break;
            case 153664:   mask   = (const float*)d_in[i]; break;
            case 49152:    qkv_w  = (const float*)d_in[i]; break;
            case 384:      qkv_b  = (const float*)d_in[i]; break;
            case 676:      relt   = (const float*)d_in[i]; break;
            case 16384:    proj_w = (const float*)d_in[i]; break;
            case 128:      proj_b = (const float*)d_in[i]; break;
            default: break;
        }
    }

    cudaFuncSetAttribute(qkv_gemm_mma,  cudaFuncAttributeMaxDynamicSharedMemorySize, SM_TOTAL);
    cudaFuncSetAttribute(proj_gemm_mma, cudaFuncAttributeMaxDynamicSharedMemorySize, SM_TOTAL);

    qkv_gemm_mma<<<TOKENS / 128, 256, SM_TOTAL>>>(x, qkv_w, qkv_b);

    attn_kernel<<<WH_TOTAL, 256>>>(relidx, mask, relt);

    proj_gemm_mma<<<TOKENS / 128, 256, SM_TOTAL>>>(proj_w, proj_b, (float*)d_out);
}

// round 6
// speedup vs baseline: 1.6652x; 1.3524x over previous
#include <cuda_runtime.h>
#include <cuda_bf16.h>
#include <cstdint>

// Swin window attention. R6 = R4 design, third submit (infra flakes R4/R5).
// All stages mma.sync tf32. B=64, H=W=56, C=128, heads=4, hd=32, ws=7, L=49.

#define TOKENS   200704
#define WH_TOTAL 16384
#define QKV_ELEMS (3ull * 16384ull * 49ull * 32ull)
#define ATT_ELEMS ((size_t)TOKENS * 128)

__device__ float g_qkv[QKV_ELEMS];   // [(s*16384 + wh)*49 + l]*32 + d
__device__ float g_att[ATT_ELEMS];   // [b,h,w,c] pre-projection

// ---------------------------------------------------------------------------
__device__ __forceinline__ uint32_t f2tf32(float x) {
    uint32_t r;
    asm("cvt.rna.tf32.f32 %0, %1;" : "=r"(r) : "f"(x));
    return r;
}
__device__ __forceinline__ void mma_tf32(float (&d)[4], const uint32_t* a, const uint32_t* b) {
    asm volatile("mma.sync.aligned.m16n8k8.row.col.f32.tf32.tf32.f32 "
                 "{%0,%1,%2,%3}, {%4,%5,%6,%7}, {%8,%9}, {%0,%1,%2,%3};"
                 : "+f"(d[0]), "+f"(d[1]), "+f"(d[2]), "+f"(d[3])
                 : "r"(a[0]), "r"(a[1]), "r"(a[2]), "r"(a[3]), "r"(b[0]), "r"(b[1]));
}

#define A_STR 132   // A smem stride (frag lane bank = 4g+t, conflict-free)
#define SM_A_BYTES (128 * A_STR * 4)   // 67584

// ---------------------------------------------------------------------------
// QKV GEMM: grid=1568, 256 threads (8 warps: 2m x 4n). A resident in smem,
// B fragments read directly from gmem (L2-resident weights). Scatter epilogue.
// ---------------------------------------------------------------------------
__global__ __launch_bounds__(256, 2) void qkv_gemm_mma(
    const float* __restrict__ A, const float* __restrict__ W,
    const float* __restrict__ bias)
{
    extern __shared__ uint32_t As[];

    int tid = threadIdx.x, bm = blockIdx.x;
    int lane = tid & 31, warp = tid >> 5;
    int g = lane >> 2, t = lane & 3;
    int m0 = (warp >> 2) * 64, n0 = (warp & 3) * 32;
    int head = warp & 3;

    // Load A tile (tf32 bits), uint4 stores
    {
        const float4* Ap = (const float4*)(A + (size_t)bm * 128 * 128);
        for (int i = tid; i < 4096; i += 256) {
            int r = i >> 5, c = (i & 31) << 2;
            float4 v = Ap[i];
            uint4 u = make_uint4(f2tf32(v.x), f2tf32(v.y), f2tf32(v.z), f2tf32(v.w));
            *(uint4*)&As[r * A_STR + c] = u;
        }
    }

    // Token mapping for this thread's 8 output rows
    int whbase[8], lwin8[8];
#pragma unroll
    for (int mt = 0; mt < 4; mt++)
#pragma unroll
        for (int h = 0; h < 2; h++) {
            int m = bm * 128 + m0 + mt * 16 + g + h * 8;
            int bimg = m / 3136;
            int rem  = m - bimg * 3136;
            int y = rem / 56, xx = rem - y * 56;
            int nhi = y / 7,  wy = y - nhi * 7;
            int nwi = xx / 7, wx = xx - nwi * 7;
            whbase[mt * 2 + h] = (bimg * 64 + nhi * 8 + nwi) * 4 + head;
            lwin8[mt * 2 + h]  = wy * 7 + wx;
        }
    __syncthreads();

#pragma unroll 1
    for (int s = 0; s < 3; s++) {
        const float* Wp = W + s * 128 + n0 + g;
        float acc[4][4][4] = {};
#pragma unroll
        for (int k0 = 0; k0 < 128; k0 += 8) {
            uint32_t b[4][2];
            const float* w0 = Wp + (size_t)(k0 + t) * 384;
            const float* w1 = w0 + 4 * 384;
#pragma unroll
            for (int nt = 0; nt < 4; nt++) {
                b[nt][0] = f2tf32(__ldg(w0 + nt * 8));
                b[nt][1] = f2tf32(__ldg(w1 + nt * 8));
            }
            uint32_t a[4][4];
#pragma unroll
            for (int mt = 0; mt < 4; mt++) {
                int base = (m0 + mt * 16 + g) * A_STR + k0 + t;
                a[mt][0] = As[base];
                a[mt][1] = As[base + 8 * A_STR];
                a[mt][2] = As[base + 4];
                a[mt][3] = As[base + 8 * A_STR + 4];
            }
#pragma unroll
            for (int mt = 0; mt < 4; mt++)
#pragma unroll
                for (int nt = 0; nt < 4; nt++)
                    mma_tf32(acc[mt][nt], a[mt], b[nt]);
        }

        // Epilogue: scatter into g_qkv window layout
        float bb[4][2];
#pragma unroll
        for (int nt = 0; nt < 4; nt++) {
            int d = nt * 8 + 2 * t;
            bb[nt][0] = bias[s * 128 + head * 32 + d];
            bb[nt][1] = bias[s * 128 + head * 32 + d + 1];
        }
#pragma unroll
        for (int mt = 0; mt < 4; mt++)
#pragma unroll
            for (int h = 0; h < 2; h++) {
                int idx = mt * 2 + h;
                size_t dst0 = ((size_t)(s * 16384 + whbase[idx]) * 49 + lwin8[idx]) * 32;
#pragma unroll
                for (int nt = 0; nt < 4; nt++) {
                    int d = nt * 8 + 2 * t;
                    float2 v = make_float2(acc[mt][nt][2 * h]     + bb[nt][0],
                                           acc[mt][nt][2 * h + 1] + bb[nt][1]);
                    *(float2*)&g_qkv[dst0 + d] = v;
                }
            }
    }
}

// ---------------------------------------------------------------------------
// Projection GEMM: grid=1568, same core, single N=128 group, linear output.
// ---------------------------------------------------------------------------
__global__ __launch_bounds__(256, 2) void proj_gemm_mma(
    const float* __restrict__ W, const float* __restrict__ bias,
    float* __restrict__ out)
{
    extern __shared__ uint32_t As[];

    int tid = threadIdx.x, bm = blockIdx.x;
    int lane = tid & 31, warp = tid >> 5;
    int g = lane >> 2, t = lane & 3;
    int m0 = (warp >> 2) * 64, n0 = (warp & 3) * 32;

    {
        const float4* Ap = (const float4*)(g_att + (size_t)bm * 128 * 128);
        for (int i = tid; i < 4096; i += 256) {
            int r = i >> 5, c = (i & 31) << 2;
            float4 v = Ap[i];
            uint4 u = make_uint4(f2tf32(v.x), f2tf32(v.y), f2tf32(v.z), f2tf32(v.w));
            *(uint4*)&As[r * A_STR + c] = u;
        }
    }
    __syncthreads();

    const float* Wp = W + n0 + g;
    float acc[4][4][4] = {};
#pragma unroll
    for (int k0 = 0; k0 < 128; k0 += 8) {
        uint32_t b[4][2];
        const float* w0 = Wp + (size_t)(k0 + t) * 128;
        const float* w1 = w0 + 4 * 128;
#pragma unroll
        for (int nt = 0; nt < 4; nt++) {
            b[nt][0] = f2tf32(__ldg(w0 + nt * 8));
            b[nt][1] = f2tf32(__ldg(w1 + nt * 8));
        }
        uint32_t a[4][4];
#pragma unroll
        for (int mt = 0; mt < 4; mt++) {
            int base = (m0 + mt * 16 + g) * A_STR + k0 + t;
            a[mt][0] = As[base];
            a[mt][1] = As[base + 8 * A_STR];
            a[mt][2] = As[base + 4];
            a[mt][3] = As[base + 8 * A_STR + 4];
        }
#pragma unroll
        for (int mt = 0; mt < 4; mt++)
#pragma unroll
            for (int nt = 0; nt < 4; nt++)
                mma_tf32(acc[mt][nt], a[mt], b[nt]);
    }

    float bb[4][2];
#pragma unroll
    for (int nt = 0; nt < 4; nt++) {
        int d = n0 + nt * 8 + 2 * t;
        bb[nt][0] = bias[d];
        bb[nt][1] = bias[d + 1];
    }
#pragma unroll
    for (int mt = 0; mt < 4; mt++)
#pragma unroll
        for (int h = 0; h < 2; h++) {
            int r = m0 + mt * 16 + g + h * 8;
            float* op = out + ((size_t)bm * 128 + r) * 128;
#pragma unroll
            for (int nt = 0; nt < 4; nt++) {
                int d = n0 + nt * 8 + 2 * t;
                float2 v = make_float2(acc[mt][nt][2 * h]     + bb[nt][0],
                                       acc[mt][nt][2 * h + 1] + bb[nt][1]);
                *(float2*)&op[d] = v;
            }
        }
}

// ---------------------------------------------------------------------------
// Attention via mma.sync tf32. One block per (window, head), 128 threads.
// S = scale*Q@K^T + bias + mask ; softmax ; O = P@V.
// ---------------------------------------------------------------------------
__global__ __launch_bounds__(128) void attn_mma(
    const int* __restrict__ relidx, const float* __restrict__ mask,
    const float* __restrict__ relt)
{
    __shared__ uint32_t sQ [64 * 36];   // tf32 Q, stride 36 (bank 4g+t)
    __shared__ uint32_t sKT[32 * 72];   // tf32 K^T [d][l], stride 72 (8t+g)
    __shared__ uint32_t sV [64 * 40];   // tf32 V  [l][d], stride 40 (8t+g)
    __shared__ float    sS [64 * 72];   // S / P, stride 72 (a-frag 8g+t)

    int tid  = threadIdx.x;
    int lane = tid & 31, warp = tid >> 5;
    int g = lane >> 2, t = lane & 3;
    int wh   = blockIdx.x;
    int head = wh & 3;
    int widx = wh >> 2;
    int bimg = widx >> 6;
    int win  = widx & 63;
    const float* qp = g_qkv + (size_t)wh * 1568;
    const float* kp = g_qkv + (size_t)(16384 + wh) * 1568;
    const float* vp = g_qkv + (size_t)(2 * 16384 + wh) * 1568;
    const float* maskp = mask + (size_t)win * 2401;

    // Load q/k/v -> tf32 smem, rows l>=49 zero
    for (int idx = tid; idx < 512; idx += 128) {
        int l = idx >> 3, c4 = (idx & 7) << 2;
        float4 q4 = make_float4(0.f, 0.f, 0.f, 0.f), k4 = q4, v4 = q4;
        if (l < 49) {
            q4 = *(const float4*)(qp + l * 32 + c4);
            k4 = *(const float4*)(kp + l * 32 + c4);
            v4 = *(const float4*)(vp + l * 32 + c4);
        }
        *(uint4*)&sQ[l * 36 + c4] = make_uint4(f2tf32(q4.x), f2tf32(q4.y), f2tf32(q4.z), f2tf32(q4.w));
        sKT[(c4 + 0) * 72 + l] = f2tf32(k4.x);
        sKT[(c4 + 1) * 72 + l] = f2tf32(k4.y);
        sKT[(c4 + 2) * 72 + l] = f2tf32(k4.z);
        sKT[(c4 + 3) * 72 + l] = f2tf32(k4.w);
        *(uint4*)&sV[l * 40 + c4] = make_uint4(f2tf32(v4.x), f2tf32(v4.y), f2tf32(v4.z), f2tf32(v4.w));
    }
    __syncthreads();

    int m0 = warp * 16;

    // ---- S strip (16 x 64) per warp ----
    {
        float acc[8][4] = {};
#pragma unroll
        for (int k0 = 0; k0 < 32; k0 += 8) {
            uint32_t a[4];
            int ab = (m0 + g) * 36 + k0 + t;
            a[0] = sQ[ab];
            a[1] = sQ[ab + 8 * 36];
            a[2] = sQ[ab + 4];
            a[3] = sQ[ab + 8 * 36 + 4];
#pragma unroll
            for (int nt = 0; nt < 8; nt++) {
                uint32_t b[2];
                int bb = (k0 + t) * 72 + nt * 8 + g;
                b[0] = sKT[bb];
                b[1] = sKT[bb + 4 * 72];
                mma_tf32(acc[nt], a, b);
            }
        }
        const float scale = 0.17677669529663687f;
#pragma unroll
        for (int h = 0; h < 2; h++) {
            int i = m0 + g + h * 8;
            if (i < 49) {
#pragma unroll
                for (int nt = 0; nt < 8; nt++) {
#pragma unroll
                    for (int e = 0; e < 2; e++) {
                        int j = nt * 8 + 2 * t + e;
                        float val = -1e30f;
                        if (j < 49) {
                            int ij = i * 49 + j;
                            val = acc[nt][2 * h + e] * scale
                                + __ldg(relt + __ldg(relidx + ij) * 4 + head)
                                + __ldg(maskp + ij);
                        }
                        sS[i * 72 + j] = val;
                    }
                }
            }
        }
    }
    __syncthreads();

    // ---- softmax (2 threads per row), write back tf32 bits ----
    {
        uint32_t* sSu = (uint32_t*)sS;
        int row = tid >> 1, q = tid & 1;
        bool valid = row < 49;
        float mx = -1e30f;
        if (valid)
            for (int j = q; j < 64; j += 2) mx = fmaxf(mx, sS[row * 72 + j]);
        mx = fmaxf(mx, __shfl_xor_sync(0xffffffffu, mx, 1));
        float sum = 0.f;
        if (valid)
            for (int j = q; j < 64; j += 2) {
                float e = __expf(sS[row * 72 + j] - mx);
                sS[row * 72 + j] = e;
                sum += e;
            }
        sum += __shfl_xor_sync(0xffffffffu, sum, 1);
        float inv = 1.f / sum;
        for (int j = q; j < 64; j += 2)
            sSu[row * 72 + j] = valid ? f2tf32(sS[row * 72 + j] * inv) : 0u;
    }
    __syncthreads();

    // ---- O strip (16 x 32) per warp ----
    {
        const uint32_t* sSu = (const uint32_t*)sS;
        float oac[4][4] = {};
#pragma unroll
        for (int k0 = 0; k0 < 64; k0 += 8) {
            uint32_t a[4];
            int ab = (m0 + g) * 72 + k0 + t;
            a[0] = sSu[ab];
            a[1] = sSu[ab + 8 * 72];
            a[2] = sSu[ab + 4];
            a[3] = sSu[ab + 8 * 72 + 4];
#pragma unroll
            for (int nt = 0; nt < 4; nt++) {
                uint32_t b[2];
                int bb = (k0 + t) * 40 + nt * 8 + g;
                b[0] = sV[bb];
                b[1] = sV[bb + 4 * 40];
                mma_tf32(oac[nt], a, b);
            }
        }
        int ybase = (win >> 3) * 7;
        int xbase = (win & 7) * 7;
#pragma unroll
        for (int h = 0; h < 2; h++) {
            int i = m0 + g + h * 8;
            if (i < 49) {
                int wy = i / 7, wx = i - wy * 7;
                float* op = g_att + (((size_t)(bimg * 56 + ybase + wy)) * 56 + (xbase + wx)) * 128
                          + head * 32;
#pragma unroll
                for (int nt = 0; nt < 4; nt++)
                    *(float2*)&op[nt * 8 + 2 * t] =
                        make_float2(oac[nt][2 * h], oac[nt][2 * h + 1]);
            }
        }
    }
}

// ---------------------------------------------------------------------------
extern "C" void kernel_launch(void* const* d_in, const int* in_sizes, int n_in,
                              void* d_out, int out_size)
{
    const float* x      = nullptr;
    const int*   relidx = nullptr;
    const float* mask   = nullptr;
    const float* qkv_w  = nullptr;
    const float* qkv_b  = nullptr;
    const float* relt   = nullptr;
    const float* proj_w = nullptr;
    const float* proj_b = nullptr;

    for (int i = 0; i < n_in; i++) {
        switch (in_sizes[i]) {
            case 25690112: x      = (const float*)d_in[i]; break;
            case 2401:     relidx = (const int*)  d_in[i]; break;
            case 153664:   mask   = (const float*)d_in[i]; break;
            case 49152:    qkv_w  = (const float*)d_in[i]; break;
            case 384:      qkv_b  = (const float*)d_in[i]; break;
            case 676:      relt   = (const float*)d_in[i]; break;
            case 16384:    proj_w = (const float*)d_in[i]; break;
            case 128:      proj_b = (const float*)d_in[i]; break;
            default: break;
        }
    }

    cudaFuncSetAttribute(qkv_gemm_mma,  cudaFuncAttributeMaxDynamicSharedMemorySize, SM_A_BYTES);
    cudaFuncSetAttribute(proj_gemm_mma, cudaFuncAttributeMaxDynamicSharedMemorySize, SM_A_BYTES);

    qkv_gemm_mma<<<TOKENS / 128, 256, SM_A_BYTES>>>(x, qkv_w, qkv_b);

    attn_mma<<<WH_TOTAL, 128>>>(relidx, mask, relt);

    proj_gemm_mma<<<TOKENS / 128, 256, SM_A_BYTES>>>(proj_w, proj_b, (float*)d_out);
}